// round 2
// baseline (speedup 1.0000x reference)
#include <cuda_runtime.h>
#include <math.h>

// Problem constants
#define NT    365
#define NGRID 2048
#define NX    32
#define NH    256
#define NG4   1024              // 4*NH
#define M_TOT (NT * NGRID)      // 747520
#define CHUNK 73                // 365 = 5 * 73
#define NCHUNK 5
#define MCH   (CHUNK * NGRID)   // rows per chunk = 149504

typedef unsigned long long ull;

// ---------------- device scratch (total ~2.14 GB; must stay well < 4GB for aarch64 link) ----
__device__ float g_x0[(size_t)M_TOT * NH];    // relu(x @ W_in^T + b_in)   765 MB
__device__ float g_xg[(size_t)MCH * NG4];     // chunked input-gate precompute  612 MB
__device__ float g_hs[(size_t)M_TOT * NH];    // hidden states per step    765 MB
__device__ float g_c [NGRID * NH];            // cell state
__device__ float g_h0[NGRID * NH];            // zero initial hidden
__device__ float g_WinT[NX * NH];             // W_in transposed [k][h]
__device__ float g_Wihr[NH * NG4];            // W_ih transposed+gate-interleaved [k][c], c=h*4+g
__device__ float g_Whhr[NH * NG4];            // W_hh transposed+gate-interleaved
__device__ float g_biasr[NG4];                // (b_ih + b_hh) gate-interleaved

// ---------------- packed f32x2 helpers ----------------
__device__ __forceinline__ ull pk2(float lo, float hi) {
    ull r;
    asm("mov.b64 %0, {%1, %2};" : "=l"(r) : "f"(lo), "f"(hi));
    return r;
}
__device__ __forceinline__ float2 upk2(ull v) {
    float2 r;
    asm("mov.b64 {%0, %1}, %2;" : "=f"(r.x), "=f"(r.y) : "l"(v));
    return r;
}
#define FMA2(d, a, b) asm("fma.rn.f32x2 %0, %1, %2, %0;" : "+l"(d) : "l"(a), "l"(b))

__device__ __forceinline__ float sigf(float x) { return 1.0f / (1.0f + expf(-x)); }

// ---------------- prep: transposes / reorders / bias fuse ----------------
__global__ void k_prep(const float* __restrict__ W_in,
                       const float* __restrict__ W_ih,
                       const float* __restrict__ b_ih,
                       const float* __restrict__ b_hh,
                       const float* __restrict__ W_hh) {
    int i = blockIdx.x * blockDim.x + threadIdx.x;
    if (i < NX * NH) {
        int k = i / NH, h = i % NH;
        g_WinT[k * NH + h] = W_in[h * NX + k];
    }
    if (i < NH * NG4) {
        int k = i / NG4, c = i % NG4;
        int h = c >> 2, g = c & 3;
        int n = g * NH + h;                 // original gate row (i,f,g,o order)
        g_Wihr[i] = W_ih[n * NH + k];
        g_Whhr[i] = W_hh[n * NH + k];
    }
    if (i < NG4) {
        int h = i >> 2, g = i & 3;
        int n = g * NH + h;
        g_biasr[i] = b_ih[n] + b_hh[n];
    }
}

__global__ void k_zero() {
    int i = blockIdx.x * blockDim.x + threadIdx.x;
    if (i < NGRID * NH) { g_h0[i] = 0.0f; g_c[i] = 0.0f; }
}

// ---------------- x0 = relu(x @ W_in^T + b_in) ----------------
// tile 128 rows x 128 cols, K = 32 (full)
__global__ __launch_bounds__(256, 1) void k_x0(const float* __restrict__ x,
                                               const float* __restrict__ b_in) {
    __shared__ float A_s[32][129];
    __shared__ float B_s[32][128];
    int tid = threadIdx.x;
    int r0 = blockIdx.x * 128;
    int c0 = blockIdx.y * 128;

    const float* Ag = x + (size_t)r0 * NX;
#pragma unroll
    for (int j = 0; j < 16; j++) {
        int idx = tid + j * 256;            // idx = row*32 + k
        A_s[idx & 31][idx >> 5] = Ag[idx];
    }
#pragma unroll
    for (int j = 0; j < 16; j++) {
        int idx = tid + j * 256;
        int k = idx >> 7, col = idx & 127;
        B_s[k][col] = g_WinT[k * NH + c0 + col];
    }
    __syncthreads();

    int tx = tid & 7, ty = tid >> 3;
    int cb = tx * 16, rb = ty * 4;

    ull acc[4][8];
#pragma unroll
    for (int p = 0; p < 8; p++) {
        ull bp = pk2(b_in[c0 + cb + 2 * p], b_in[c0 + cb + 2 * p + 1]);
        acc[0][p] = bp; acc[1][p] = bp; acc[2][p] = bp; acc[3][p] = bp;
    }
#pragma unroll
    for (int kk = 0; kk < 32; kk++) {
        ull a2[4];
#pragma unroll
        for (int i = 0; i < 4; i++) { float a = A_s[kk][rb + i]; a2[i] = pk2(a, a); }
        const ull* bs = reinterpret_cast<const ull*>(&B_s[kk][cb]);
        ull b2[8];
#pragma unroll
        for (int p = 0; p < 8; p++) b2[p] = bs[p];
#pragma unroll
        for (int i = 0; i < 4; i++)
#pragma unroll
            for (int p = 0; p < 8; p++) FMA2(acc[i][p], a2[i], b2[p]);
    }
#pragma unroll
    for (int i = 0; i < 4; i++) {
        size_t r = (size_t)(r0 + rb + i);
        float4* dst = reinterpret_cast<float4*>(&g_x0[r * NH + c0 + cb]);
#pragma unroll
        for (int p = 0; p < 4; p++) {
            float2 u0 = upk2(acc[i][2 * p]);
            float2 u1 = upk2(acc[i][2 * p + 1]);
            dst[p] = make_float4(fmaxf(u0.x, 0.f), fmaxf(u0.y, 0.f),
                                 fmaxf(u1.x, 0.f), fmaxf(u1.y, 0.f));
        }
    }
}

// ---------------- xg = x0 @ Wihr + biasr  (gate-interleaved, one time-chunk) ----------------
// tile 128x128, K=256 in chunks of 16; rows are chunk-local
__global__ __launch_bounds__(256, 1) void k_xg(int chunk) {
    __shared__ float A_s[16][129];
    __shared__ float B_s[16][128];
    int tid = threadIdx.x;
    int r0 = blockIdx.x * 128;                        // chunk-local row
    int c0 = blockIdx.y * 128;
    size_t rowbase = (size_t)chunk * MCH;             // global row offset into g_x0

    int tx = tid & 7, ty = tid >> 3;
    int cb = tx * 16, rb = ty * 4;

    ull acc[4][8];
#pragma unroll
    for (int p = 0; p < 8; p++) {
        ull bp = pk2(g_biasr[c0 + cb + 2 * p], g_biasr[c0 + cb + 2 * p + 1]);
        acc[0][p] = bp; acc[1][p] = bp; acc[2][p] = bp; acc[3][p] = bp;
    }

    for (int k0 = 0; k0 < NH; k0 += 16) {
        __syncthreads();
#pragma unroll
        for (int j = 0; j < 8; j++) {
            int idx = tid + j * 256;        // idx = row*16 + k
            int row = idx >> 4, k = idx & 15;
            A_s[k][row] = g_x0[(rowbase + r0 + row) * NH + k0 + k];
        }
#pragma unroll
        for (int j = 0; j < 8; j++) {
            int idx = tid + j * 256;
            int k = idx >> 7, col = idx & 127;
            B_s[k][col] = g_Wihr[(k0 + k) * NG4 + c0 + col];
        }
        __syncthreads();
#pragma unroll
        for (int kk = 0; kk < 16; kk++) {
            ull a2[4];
#pragma unroll
            for (int i = 0; i < 4; i++) { float a = A_s[kk][rb + i]; a2[i] = pk2(a, a); }
            const ull* bs = reinterpret_cast<const ull*>(&B_s[kk][cb]);
            ull b2[8];
#pragma unroll
            for (int p = 0; p < 8; p++) b2[p] = bs[p];
#pragma unroll
            for (int i = 0; i < 4; i++)
#pragma unroll
                for (int p = 0; p < 8; p++) FMA2(acc[i][p], a2[i], b2[p]);
        }
    }
#pragma unroll
    for (int i = 0; i < 4; i++) {
        size_t r = (size_t)(r0 + rb + i);
        float4* dst = reinterpret_cast<float4*>(&g_xg[r * NG4 + c0 + cb]);
#pragma unroll
        for (int p = 0; p < 4; p++) {
            float2 u0 = upk2(acc[i][2 * p]);
            float2 u1 = upk2(acc[i][2 * p + 1]);
            dst[p] = make_float4(u0.x, u0.y, u1.x, u1.y);
        }
    }
}

// ---------------- per-timestep fused GEMM + LSTM cell ----------------
// gates = xg[t_local] + hprev @ Whhr; cell update; h -> hs[t]
__global__ __launch_bounds__(256, 1) void k_step(int t, int tloc) {
    const float* __restrict__ hprev =
        (t == 0) ? g_h0 : (g_hs + (size_t)(t - 1) * NGRID * NH);

    __shared__ float A_s[16][129];
    __shared__ float B_s[16][128];
    int tid = threadIdx.x;
    int r0 = blockIdx.x * 128;
    int c0 = blockIdx.y * 128;

    int tx = tid & 7, ty = tid >> 3;
    int cb = tx * 16, rb = ty * 4;

    ull acc[4][8];
#pragma unroll
    for (int i = 0; i < 4; i++)
#pragma unroll
        for (int p = 0; p < 8; p++) acc[i][p] = 0ULL;

    for (int k0 = 0; k0 < NH; k0 += 16) {
        __syncthreads();
#pragma unroll
        for (int j = 0; j < 8; j++) {
            int idx = tid + j * 256;
            int row = idx >> 4, k = idx & 15;
            A_s[k][row] = hprev[(size_t)(r0 + row) * NH + k0 + k];
        }
#pragma unroll
        for (int j = 0; j < 8; j++) {
            int idx = tid + j * 256;
            int k = idx >> 7, col = idx & 127;
            B_s[k][col] = g_Whhr[(k0 + k) * NG4 + c0 + col];
        }
        __syncthreads();
#pragma unroll
        for (int kk = 0; kk < 16; kk++) {
            ull a2[4];
#pragma unroll
            for (int i = 0; i < 4; i++) { float a = A_s[kk][rb + i]; a2[i] = pk2(a, a); }
            const ull* bs = reinterpret_cast<const ull*>(&B_s[kk][cb]);
            ull b2[8];
#pragma unroll
            for (int p = 0; p < 8; p++) b2[p] = bs[p];
#pragma unroll
            for (int i = 0; i < 4; i++)
#pragma unroll
                for (int p = 0; p < 8; p++) FMA2(acc[i][p], a2[i], b2[p]);
        }
    }

    // epilogue: gate quads (i,f,g,o) are contiguous in interleaved layout
    int h0 = (c0 + cb) >> 2;
#pragma unroll
    for (int i = 0; i < 4; i++) {
        int r = r0 + rb + i;
        const float4* xg4 = reinterpret_cast<const float4*>(
            &g_xg[((size_t)tloc * NGRID + r) * NG4 + c0 + cb]);
#pragma unroll
        for (int hq = 0; hq < 4; hq++) {
            float2 u0 = upk2(acc[i][2 * hq]);       // (i, f)
            float2 u1 = upk2(acc[i][2 * hq + 1]);   // (g, o)
            float4 xg = xg4[hq];
            float iv = u0.x + xg.x;
            float fv = u0.y + xg.y;
            float gv = u1.x + xg.z;
            float ov = u1.y + xg.w;
            int ci = r * NH + h0 + hq;
            float cp = g_c[ci];
            float cn = sigf(fv) * cp + sigf(iv) * tanhf(gv);
            g_c[ci] = cn;
            g_hs[(size_t)t * NGRID * NH + ci] = sigf(ov) * tanhf(cn);
        }
    }
}

// ---------------- output head: out = hs @ W_out^T + b_out (NY=1) ----------------
__global__ __launch_bounds__(256) void k_out(const float* __restrict__ W_out,
                                             const float* __restrict__ b_out,
                                             float* __restrict__ out) {
    __shared__ float Ws[NH];
    int tid = threadIdx.x;
    Ws[tid] = W_out[tid];
    __syncthreads();
    int w = tid >> 5, l = tid & 31;
    size_t r = (size_t)blockIdx.x * 8 + w;
    const float* hr = g_hs + r * NH;
    float s = 0.0f;
#pragma unroll
    for (int j = 0; j < 8; j++) s += hr[l + j * 32] * Ws[l + j * 32];
#pragma unroll
    for (int o = 16; o > 0; o >>= 1) s += __shfl_down_sync(0xffffffffu, s, o);
    if (l == 0) out[r] = s + b_out[0];
}

// ---------------- launch ----------------
extern "C" void kernel_launch(void* const* d_in, const int* in_sizes, int n_in,
                              void* d_out, int out_size) {
    const float* x     = (const float*)d_in[0];
    const float* W_in  = (const float*)d_in[1];
    const float* b_in  = (const float*)d_in[2];
    const float* W_ih  = (const float*)d_in[3];
    const float* b_ih  = (const float*)d_in[4];
    const float* W_hh  = (const float*)d_in[5];
    const float* b_hh  = (const float*)d_in[6];
    const float* W_out = (const float*)d_in[7];
    const float* b_out = (const float*)d_in[8];
    float* out = (float*)d_out;

    k_prep<<<(NH * NG4 + 255) / 256, 256>>>(W_in, W_ih, b_ih, b_hh, W_hh);
    k_zero<<<(NGRID * NH + 255) / 256, 256>>>();
    k_x0<<<dim3(M_TOT / 128, NH / 128), 256>>>(x, b_in);
    for (int chunk = 0; chunk < NCHUNK; chunk++) {
        k_xg<<<dim3(MCH / 128, NG4 / 128), 256>>>(chunk);
        for (int tl = 0; tl < CHUNK; tl++) {
            int t = chunk * CHUNK + tl;
            k_step<<<dim3(NGRID / 128, NG4 / 128), 256>>>(t, tl);
        }
    }
    k_out<<<M_TOT / 8, 256>>>(W_out, b_out, out);
}

// round 3
// speedup vs baseline: 1.7952x; 1.7952x over previous
#include <cuda_runtime.h>
#include <math.h>

// Problem constants
#define NT    365
#define NGRID 2048
#define NX    32
#define NH    256
#define NG4   1024
#define M_TOT (NT * NGRID)      // 747520
#define CHUNK 73                // 365 = 5 * 73
#define NCHUNK 5
#define MCH   (CHUNK * NGRID)   // 149504 rows per chunk

#define PADW 68                 // W_s row pitch (floats)
#define PADA 132                // A_s row pitch (floats)
#define NBLK 256                // persistent scan grid (16 row x 16 col tiles)
#define SMEM_BYTES ((NH * PADW + 2 * 16 * PADA) * 4)   // 86528 B

typedef unsigned long long ull;

// ---------------- device scratch (~2.14 GB total; keep < 4GB for aarch64 link) ----
__device__ float g_x0[(size_t)M_TOT * NH];    // 765 MB
__device__ float g_xg[(size_t)MCH * NG4];     // 612 MB (per-chunk ring)
__device__ float g_hs[(size_t)M_TOT * NH];    // 765 MB
__device__ float g_c [NGRID * NH];            // cell state spill between chunks
__device__ float g_WinT[NX * NH];
__device__ float g_Wihr[NH * NG4];            // W_ih^T, gate-interleaved cols (c = h*4+g)
__device__ float g_Whhr[NH * NG4];            // W_hh^T, gate-interleaved cols
__device__ float g_biasr[NG4];                // b_ih + b_hh, gate-interleaved
__device__ unsigned g_bar_cnt;                // grid barrier (self-resetting)
__device__ unsigned g_bar_gen;

// ---------------- packed f32x2 helpers ----------------
__device__ __forceinline__ ull pk2(float lo, float hi) {
    ull r;
    asm("mov.b64 %0, {%1, %2};" : "=l"(r) : "f"(lo), "f"(hi));
    return r;
}
__device__ __forceinline__ float2 upk2(ull v) {
    float2 r;
    asm("mov.b64 {%0, %1}, %2;" : "=f"(r.x), "=f"(r.y) : "l"(v));
    return r;
}
#define FMA2(d, a, b) asm("fma.rn.f32x2 %0, %1, %2, %0;" : "+l"(d) : "l"(a), "l"(b))

__device__ __forceinline__ float sigf(float x) { return 1.0f / (1.0f + expf(-x)); }

// ---------------- grid-wide barrier (all NBLK blocks resident) ----------------
__device__ __forceinline__ void grid_sync() {
    __syncthreads();
    if (threadIdx.x == 0) {
        __threadfence();
        unsigned gen = *((volatile unsigned*)&g_bar_gen);
        if (atomicAdd(&g_bar_cnt, 1u) == (NBLK - 1)) {
            g_bar_cnt = 0;
            __threadfence();
            atomicExch(&g_bar_gen, gen + 1);
        } else {
            while (*((volatile unsigned*)&g_bar_gen) == gen) __nanosleep(32);
        }
        __threadfence();
    }
    __syncthreads();
}

// ---------------- prep: transposes / reorders / bias fuse ----------------
__global__ void k_prep(const float* __restrict__ W_in,
                       const float* __restrict__ W_ih,
                       const float* __restrict__ b_ih,
                       const float* __restrict__ b_hh,
                       const float* __restrict__ W_hh) {
    int i = blockIdx.x * blockDim.x + threadIdx.x;
    if (i < NX * NH) {
        int k = i / NH, h = i % NH;
        g_WinT[k * NH + h] = W_in[h * NX + k];
    }
    if (i < NH * NG4) {
        int k = i / NG4, c = i % NG4;
        int h = c >> 2, g = c & 3;
        int n = g * NH + h;                 // original gate row (i,f,g,o)
        g_Wihr[i] = W_ih[n * NH + k];
        g_Whhr[i] = W_hh[n * NH + k];
    }
    if (i < NG4) {
        int h = i >> 2, g = i & 3;
        int n = g * NH + h;
        g_biasr[i] = b_ih[n] + b_hh[n];
    }
}

// ---------------- x0 = relu(x @ W_in^T + b_in) ----------------
__global__ __launch_bounds__(256, 1) void k_x0(const float* __restrict__ x,
                                               const float* __restrict__ b_in) {
    __shared__ float A_s[32][129];
    __shared__ float B_s[32][128];
    int tid = threadIdx.x;
    int r0 = blockIdx.x * 128;
    int c0 = blockIdx.y * 128;

    const float* Ag = x + (size_t)r0 * NX;
#pragma unroll
    for (int j = 0; j < 16; j++) {
        int idx = tid + j * 256;
        A_s[idx & 31][idx >> 5] = Ag[idx];
    }
#pragma unroll
    for (int j = 0; j < 16; j++) {
        int idx = tid + j * 256;
        int k = idx >> 7, col = idx & 127;
        B_s[k][col] = g_WinT[k * NH + c0 + col];
    }
    __syncthreads();

    int tx = tid & 7, ty = tid >> 3;
    int cb = tx * 16, rb = ty * 4;

    ull acc[4][8];
#pragma unroll
    for (int p = 0; p < 8; p++) {
        ull bp = pk2(b_in[c0 + cb + 2 * p], b_in[c0 + cb + 2 * p + 1]);
        acc[0][p] = bp; acc[1][p] = bp; acc[2][p] = bp; acc[3][p] = bp;
    }
#pragma unroll
    for (int kk = 0; kk < 32; kk++) {
        ull a2[4];
#pragma unroll
        for (int i = 0; i < 4; i++) { float a = A_s[kk][rb + i]; a2[i] = pk2(a, a); }
        const ull* bs = reinterpret_cast<const ull*>(&B_s[kk][cb]);
        ull b2[8];
#pragma unroll
        for (int p = 0; p < 8; p++) b2[p] = bs[p];
#pragma unroll
        for (int i = 0; i < 4; i++)
#pragma unroll
            for (int p = 0; p < 8; p++) FMA2(acc[i][p], a2[i], b2[p]);
    }
#pragma unroll
    for (int i = 0; i < 4; i++) {
        size_t r = (size_t)(r0 + rb + i);
        float4* dst = reinterpret_cast<float4*>(&g_x0[r * NH + c0 + cb]);
#pragma unroll
        for (int p = 0; p < 4; p++) {
            float2 u0 = upk2(acc[i][2 * p]);
            float2 u1 = upk2(acc[i][2 * p + 1]);
            dst[p] = make_float4(fmaxf(u0.x, 0.f), fmaxf(u0.y, 0.f),
                                 fmaxf(u1.x, 0.f), fmaxf(u1.y, 0.f));
        }
    }
}

// ---------------- shared GEMM building blocks (128 rows x 64 cols per block) ------
__device__ __forceinline__ void load_wtile(float* W_s, const float* __restrict__ Wg,
                                           int c0, int tid) {
#pragma unroll
    for (int j = 0; j < 16; j++) {
        int q = tid + j * 256;
        int k = q >> 4, col4 = q & 15;
        *reinterpret_cast<float4*>(&W_s[k * PADW + col4 * 4]) =
            *reinterpret_cast<const float4*>(&Wg[(size_t)k * NG4 + c0 + col4 * 4]);
    }
}

__device__ __forceinline__ void sts_a(float* Ad, int arow, int akq, float4 p0, float4 p1) {
    Ad[(akq + 0) * PADA + arow] = p0.x;
    Ad[(akq + 1) * PADA + arow] = p0.y;
    Ad[(akq + 2) * PADA + arow] = p0.z;
    Ad[(akq + 3) * PADA + arow] = p0.w;
    int r2 = arow + 64;
    Ad[(akq + 0) * PADA + r2] = p1.x;
    Ad[(akq + 1) * PADA + r2] = p1.y;
    Ad[(akq + 2) * PADA + r2] = p1.z;
    Ad[(akq + 3) * PADA + r2] = p1.w;
}

__device__ __forceinline__ void gemm_chunk(const float* __restrict__ Ad,
                                           const float* __restrict__ W_s,
                                           int k0, int tx, int ty, ull acc[4][4]) {
#pragma unroll
    for (int kk = 0; kk < 16; kk++) {
        float4 av = *reinterpret_cast<const float4*>(&Ad[kk * PADA + ty * 4]);
        ull a2[4];
        a2[0] = pk2(av.x, av.x); a2[1] = pk2(av.y, av.y);
        a2[2] = pk2(av.z, av.z); a2[3] = pk2(av.w, av.w);
        const float* wr = &W_s[(k0 + kk) * PADW + tx * 8];
        ulonglong2 wa = *reinterpret_cast<const ulonglong2*>(wr);
        ulonglong2 wb = *reinterpret_cast<const ulonglong2*>(wr + 4);
#pragma unroll
        for (int i = 0; i < 4; i++) {
            FMA2(acc[i][0], a2[i], wa.x);
            FMA2(acc[i][1], a2[i], wa.y);
            FMA2(acc[i][2], a2[i], wb.x);
            FMA2(acc[i][3], a2[i], wb.y);
        }
    }
}

// ---------------- xg = x0 @ Wihr + biasr (one time-chunk) ----------------
// grid (MCH/128, 16), weights-resident smem, double-buffered A
__global__ __launch_bounds__(256, 2) void k_xg2(int chunk) {
    extern __shared__ float sm[];
    float* W_s = sm;                   // [256][PADW]
    float* A_s = sm + NH * PADW;       // [2][16][PADA]
    int tid = threadIdx.x;
    int c0 = blockIdx.y * 64;
    size_t rowbase = (size_t)chunk * MCH + (size_t)blockIdx.x * 128;
    int tx = tid & 7, ty = tid >> 3;

    load_wtile(W_s, g_Wihr, c0, tid);

    ull acc[4][4];
#pragma unroll
    for (int j = 0; j < 4; j++) {
        ull bp = pk2(g_biasr[c0 + tx * 8 + 2 * j], g_biasr[c0 + tx * 8 + 2 * j + 1]);
        acc[0][j] = bp; acc[1][j] = bp; acc[2][j] = bp; acc[3][j] = bp;
    }
    __syncthreads();

    int arow = tid >> 2, akq = (tid & 3) * 4;
    const float* Ag = g_x0 + rowbase * NH;
    float4 pa0 = *reinterpret_cast<const float4*>(&Ag[(size_t)arow * NH + akq]);
    float4 pa1 = *reinterpret_cast<const float4*>(&Ag[(size_t)(arow + 64) * NH + akq]);

#pragma unroll 1
    for (int c = 0; c < 16; c++) {
        float* Ad = A_s + (c & 1) * 16 * PADA;
        sts_a(Ad, arow, akq, pa0, pa1);
        if (c < 15) {
            int kn = (c + 1) * 16 + akq;
            pa0 = *reinterpret_cast<const float4*>(&Ag[(size_t)arow * NH + kn]);
            pa1 = *reinterpret_cast<const float4*>(&Ag[(size_t)(arow + 64) * NH + kn]);
        }
        __syncthreads();
        gemm_chunk(Ad, W_s, c * 16, tx, ty, acc);
    }

#pragma unroll
    for (int i = 0; i < 4; i++) {
        size_t r = (size_t)blockIdx.x * 128 + ty * 4 + i;
        float* dst = &g_xg[r * NG4 + c0 + tx * 8];
        float2 u0 = upk2(acc[i][0]), u1 = upk2(acc[i][1]);
        float2 u2 = upk2(acc[i][2]), u3 = upk2(acc[i][3]);
        *reinterpret_cast<float4*>(dst)     = make_float4(u0.x, u0.y, u1.x, u1.y);
        *reinterpret_cast<float4*>(dst + 4) = make_float4(u2.x, u2.y, u3.x, u3.y);
    }
}

// ---------------- persistent scan: 73 LSTM steps, weights + c resident ----------
__global__ __launch_bounds__(256, 2) void k_scan(int chunk) {
    extern __shared__ float sm[];
    float* W_s = sm;
    float* A_s = sm + NH * PADW;
    int tid = threadIdx.x;
    int cbk = blockIdx.x & 15;          // 16 col tiles of 64 gate-cols
    int rbk = blockIdx.x >> 4;          // 16 row tiles of 128 rows
    int c0 = cbk * 64;
    int tx = tid & 7, ty = tid >> 3;
    int h0 = cbk * 16 + tx * 2;         // first of 2 h indices this thread owns
    int arow = tid >> 2, akq = (tid & 3) * 4;

    load_wtile(W_s, g_Whhr, c0, tid);

    float creg[4][2];
#pragma unroll
    for (int i = 0; i < 4; i++) {
        int r = rbk * 128 + ty * 4 + i;
        if (chunk == 0) { creg[i][0] = 0.f; creg[i][1] = 0.f; }
        else {
            creg[i][0] = g_c[r * NH + h0];
            creg[i][1] = g_c[r * NH + h0 + 1];
        }
    }
    __syncthreads();

    for (int tl = 0; tl < CHUNK; tl++) {
        int t = chunk * CHUNK + tl;
        ull acc[4][4];
#pragma unroll
        for (int i = 0; i < 4; i++)
#pragma unroll
            for (int j = 0; j < 4; j++) acc[i][j] = 0ULL;

        if (t > 0) {
            const float* hp = g_hs + (size_t)(t - 1) * NGRID * NH + (size_t)rbk * 128 * NH;
            float4 pa0 = __ldcg(reinterpret_cast<const float4*>(&hp[(size_t)arow * NH + akq]));
            float4 pa1 = __ldcg(reinterpret_cast<const float4*>(&hp[(size_t)(arow + 64) * NH + akq]));
#pragma unroll 1
            for (int c = 0; c < 16; c++) {
                float* Ad = A_s + (c & 1) * 16 * PADA;
                sts_a(Ad, arow, akq, pa0, pa1);
                if (c < 15) {
                    int kn = (c + 1) * 16 + akq;
                    pa0 = __ldcg(reinterpret_cast<const float4*>(&hp[(size_t)arow * NH + kn]));
                    pa1 = __ldcg(reinterpret_cast<const float4*>(&hp[(size_t)(arow + 64) * NH + kn]));
                }
                __syncthreads();
                gemm_chunk(Ad, W_s, c * 16, tx, ty, acc);
            }
            __syncthreads();   // protect A_s before next step's first STS
        }

        // epilogue: gates -> cell update -> h
#pragma unroll
        for (int i = 0; i < 4; i++) {
            int r = rbk * 128 + ty * 4 + i;
            const float* xgr = &g_xg[((size_t)tl * NGRID + r) * NG4 + c0 + tx * 8];
            float4 x0v = __ldg(reinterpret_cast<const float4*>(xgr));
            float4 x1v = __ldg(reinterpret_cast<const float4*>(xgr + 4));
            float2 g0 = upk2(acc[i][0]), g1 = upk2(acc[i][1]);
            float2 g2 = upk2(acc[i][2]), g3 = upk2(acc[i][3]);
            float iv0 = g0.x + x0v.x, fv0 = g0.y + x0v.y;
            float gv0 = g1.x + x0v.z, ov0 = g1.y + x0v.w;
            float iv1 = g2.x + x1v.x, fv1 = g2.y + x1v.y;
            float gv1 = g3.x + x1v.z, ov1 = g3.y + x1v.w;
            float cn0 = sigf(fv0) * creg[i][0] + sigf(iv0) * tanhf(gv0);
            float cn1 = sigf(fv1) * creg[i][1] + sigf(iv1) * tanhf(gv1);
            creg[i][0] = cn0; creg[i][1] = cn1;
            float h0v = sigf(ov0) * tanhf(cn0);
            float h1v = sigf(ov1) * tanhf(cn1);
            *reinterpret_cast<float2*>(&g_hs[((size_t)t * NGRID + r) * NH + h0]) =
                make_float2(h0v, h1v);
        }

        if (tl < CHUNK - 1) grid_sync();
    }

    // spill c for next chunk
#pragma unroll
    for (int i = 0; i < 4; i++) {
        int r = rbk * 128 + ty * 4 + i;
        g_c[r * NH + h0]     = creg[i][0];
        g_c[r * NH + h0 + 1] = creg[i][1];
    }
}

// ---------------- output head: out = hs @ W_out^T + b_out (NY=1) ----------------
__global__ __launch_bounds__(256) void k_out(const float* __restrict__ W_out,
                                             const float* __restrict__ b_out,
                                             float* __restrict__ out) {
    __shared__ float Ws[NH];
    int tid = threadIdx.x;
    Ws[tid] = W_out[tid];
    __syncthreads();
    int w = tid >> 5, l = tid & 31;
    size_t r = (size_t)blockIdx.x * 8 + w;
    const float* hr = g_hs + r * NH;
    float s = 0.0f;
#pragma unroll
    for (int j = 0; j < 8; j++) s += hr[l + j * 32] * Ws[l + j * 32];
#pragma unroll
    for (int o = 16; o > 0; o >>= 1) s += __shfl_down_sync(0xffffffffu, s, o);
    if (l == 0) out[r] = s + b_out[0];
}

// ---------------- launch ----------------
extern "C" void kernel_launch(void* const* d_in, const int* in_sizes, int n_in,
                              void* d_out, int out_size) {
    const float* x     = (const float*)d_in[0];
    const float* W_in  = (const float*)d_in[1];
    const float* b_in  = (const float*)d_in[2];
    const float* W_ih  = (const float*)d_in[3];
    const float* b_ih  = (const float*)d_in[4];
    const float* W_hh  = (const float*)d_in[5];
    const float* b_hh  = (const float*)d_in[6];
    const float* W_out = (const float*)d_in[7];
    const float* b_out = (const float*)d_in[8];
    float* out = (float*)d_out;

    static int attr_done = 0;
    if (!attr_done) {
        cudaFuncSetAttribute(k_xg2,  cudaFuncAttributeMaxDynamicSharedMemorySize, SMEM_BYTES);
        cudaFuncSetAttribute(k_scan, cudaFuncAttributeMaxDynamicSharedMemorySize, SMEM_BYTES);
        attr_done = 1;
    }

    k_prep<<<(NH * NG4 + 255) / 256, 256>>>(W_in, W_ih, b_ih, b_hh, W_hh);
    k_x0<<<dim3(M_TOT / 128, NH / 128), 256>>>(x, b_in);
    for (int chunk = 0; chunk < NCHUNK; chunk++) {
        k_xg2<<<dim3(MCH / 128, 16), 256, SMEM_BYTES>>>(chunk);
        k_scan<<<NBLK, 256, SMEM_BYTES>>>(chunk);
    }
    k_out<<<M_TOT / 8, 256>>>(W_out, b_out, out);
}

// round 5
// speedup vs baseline: 4.8918x; 2.7249x over previous
#include <cuda_runtime.h>
#include <cuda_bf16.h>
#include <math.h>
#include <stdint.h>

// ---------------- problem constants ----------------
#define NT    365
#define NGRID 2048
#define NX    32
#define NH    256
#define NG4   1024
#define M_TOT (NT * NGRID)        // 747520
#define CHUNK 73                  // 365 = 5*73
#define NCHUNK 5
#define MCH   (CHUNK * NGRID)     // 149504

#define NBLK  128                 // persistent scan CTAs (16 M x 8 N)
// dynamic SMEM: W hi tiles [0,65536), W lo [65536,131072), A bufs [131072,196608)
#define AOFF  131072
#define DSMEM 196608

// ---------------- device globals (~1.5 GB) ----------------
__device__ __nv_bfloat16 g_x0h[(size_t)M_TOT * NH];   // 383 MB
__device__ __nv_bfloat16 g_x0l[(size_t)M_TOT * NH];   // 383 MB
__device__ float g_xg[(size_t)MCH * NG4];             // 612 MB (per-chunk ring)
__device__ __nv_bfloat16 g_hh[2 * NGRID * NH];        // h ring (2 steps) hi
__device__ __nv_bfloat16 g_hl[2 * NGRID * NH];        // lo
__device__ float g_part[(size_t)M_TOT * 32];          // 96 MB partial out dots
__device__ float g_c[NGRID * NH];                     // c spill between chunks
__device__ float g_WinT[NX * NH];
__device__ __nv_bfloat16 g_Wih_h[NG4 * NH], g_Wih_l[NG4 * NH];  // [c][k], c=h*4+g
__device__ __nv_bfloat16 g_Whh_h[NG4 * NH], g_Whh_l[NG4 * NH];
__device__ float g_biasr[NG4];
__device__ unsigned g_bar_cnt, g_bar_gen;

// ---------------- helpers ----------------
__device__ __forceinline__ float sigf(float x) { return 1.0f / (1.0f + expf(-x)); }

__device__ __forceinline__ uint32_t smem_u32(const void* p) {
    uint32_t a;
    asm("{ .reg .u64 t; cvta.to.shared.u64 t, %1; cvt.u32.u64 %0, t; }" : "=r"(a) : "l"(p));
    return a;
}

// SW128-swizzled byte address inside a 128row x 64col bf16 tile
__device__ __forceinline__ uint32_t tadr(uint32_t tb, int row, int kcol) {
    uint32_t bo = (uint32_t)(row * 128 + kcol * 2);
    return tb + (bo ^ ((bo >> 3) & 0x70));
}

__device__ __forceinline__ void ldsm4(uint32_t* r, uint32_t addr) {
    asm volatile("ldmatrix.sync.aligned.m8n8.x4.shared.b16 {%0,%1,%2,%3}, [%4];"
                 : "=r"(r[0]), "=r"(r[1]), "=r"(r[2]), "=r"(r[3]) : "r"(addr));
}

__device__ __forceinline__ void mma16816(float* d, const uint32_t* a, const uint32_t* b) {
    asm volatile("mma.sync.aligned.m16n8k16.row.col.f32.bf16.bf16.f32 "
                 "{%0,%1,%2,%3}, {%4,%5,%6,%7}, {%8,%9}, {%0,%1,%2,%3};"
                 : "+f"(d[0]), "+f"(d[1]), "+f"(d[2]), "+f"(d[3])
                 : "r"(a[0]), "r"(a[1]), "r"(a[2]), "r"(a[3]), "r"(b[0]), "r"(b[1]));
}

// global -> regs (one 128x64 bf16 tile, row pitch 256 elems = 512B)
__device__ __forceinline__ void ldg_tile(uint4* R, const __nv_bfloat16* __restrict__ g, int tid) {
    const char* gp = (const char*)g;
#pragma unroll
    for (int j = 0; j < 4; j++) {
        int q = tid + j * 256;
        int row = q >> 3, ch = q & 7;
        R[j] = __ldcg((const uint4*)(gp + (size_t)row * 512 + ch * 16));
    }
}
// regs -> SW128-swizzled smem tile
__device__ __forceinline__ void sts_tile(uint32_t dst, const uint4* R, int tid) {
#pragma unroll
    for (int j = 0; j < 4; j++) {
        int q = tid + j * 256;
        int row = q >> 3, ch = q & 7;
        uint32_t bo = (uint32_t)(row * 128 + ch * 16);
        uint32_t off = dst + (bo ^ ((bo >> 3) & 0x70));
        asm volatile("st.shared.v4.b32 [%0], {%1,%2,%3,%4};"
                     :: "r"(off), "r"(R[j].x), "r"(R[j].y), "r"(R[j].z), "r"(R[j].w));
    }
}
__device__ __forceinline__ void ld_tile(uint32_t dst, const __nv_bfloat16* __restrict__ g, int tid) {
    uint4 R[4];
    ldg_tile(R, g, tid);
    sts_tile(dst, R, tid);
}

// one 64-wide K chunk: 3-term split (Ahi*Whi + Alo*Whi + Ahi*Wlo), 4 k16 steps
__device__ __forceinline__ void mma_chunk(uint32_t abuf, uint32_t whi, uint32_t wlo,
                                          float acc[4][4][4], int mrow, int nbase,
                                          int rowAl, int kselA, int rowBl, int kselB) {
    uint32_t ahi = abuf, alo = abuf + 16384;
#pragma unroll
    for (int ks = 0; ks < 4; ks++) {
        int kA = ks * 16 + kselA, kB = ks * 16 + kselB;
        uint32_t Ah[4][4], Al[4][4], Wh[2][4], Wl[2][4];
#pragma unroll
        for (int mf = 0; mf < 4; mf++) {
            int row = mrow + mf * 16 + rowAl;
            ldsm4(Ah[mf], tadr(ahi, row, kA));
            ldsm4(Al[mf], tadr(alo, row, kA));
        }
#pragma unroll
        for (int np = 0; np < 2; np++) {
            int n = nbase + np * 16 + rowBl;
            ldsm4(Wh[np], tadr(whi, n, kB));
            ldsm4(Wl[np], tadr(wlo, n, kB));
        }
#pragma unroll
        for (int mf = 0; mf < 4; mf++)
#pragma unroll
            for (int nf = 0; nf < 4; nf++) {
                const uint32_t* bh = &Wh[nf >> 1][(nf & 1) * 2];
                const uint32_t* bl = &Wl[nf >> 1][(nf & 1) * 2];
                mma16816(acc[mf][nf], Ah[mf], bh);
                mma16816(acc[mf][nf], Al[mf], bh);
                mma16816(acc[mf][nf], Ah[mf], bl);
            }
    }
}

// ---------------- grid barrier (NBLK resident CTAs) ----------------
__device__ __forceinline__ void grid_sync() {
    __syncthreads();
    if (threadIdx.x == 0) {
        __threadfence();
        unsigned gen = *((volatile unsigned*)&g_bar_gen);
        if (atomicAdd(&g_bar_cnt, 1u) == (NBLK - 1)) {
            g_bar_cnt = 0;
            __threadfence();
            atomicExch(&g_bar_gen, gen + 1);
        } else {
            while (*((volatile unsigned*)&g_bar_gen) == gen) __nanosleep(32);
        }
        __threadfence();
    }
    __syncthreads();
}

// ---------------- prep ----------------
__global__ void k_prep(const float* __restrict__ W_in,
                       const float* __restrict__ W_ih,
                       const float* __restrict__ b_ih,
                       const float* __restrict__ b_hh,
                       const float* __restrict__ W_hh) {
    int i = blockIdx.x * blockDim.x + threadIdx.x;
    if (i < NX * NH) {
        int k = i / NH, h = i % NH;
        g_WinT[k * NH + h] = W_in[h * NX + k];
    }
    if (i < NG4 * NH) {                      // i = c*256 + k
        int c = i >> 8, k = i & 255;
        int h = c >> 2, g = c & 3;
        int n = g * NH + h;
        float wih = W_ih[n * NH + k];
        float whh = W_hh[n * NH + k];
        __nv_bfloat16 ih_h = __float2bfloat16(wih);
        __nv_bfloat16 hh_h = __float2bfloat16(whh);
        g_Wih_h[i] = ih_h;
        g_Wih_l[i] = __float2bfloat16(wih - __bfloat162float(ih_h));
        g_Whh_h[i] = hh_h;
        g_Whh_l[i] = __float2bfloat16(whh - __bfloat162float(hh_h));
    }
    if (i < NG4) {
        int h = i >> 2, g = i & 3;
        int n = g * NH + h;
        g_biasr[i] = b_ih[n] + b_hh[n];
    }
}

// ---------------- x0 = relu(x @ W_in^T + b_in) -> bf16 hi/lo ----------------
typedef unsigned long long u64t;
__device__ __forceinline__ u64t pk2(float lo, float hi) {
    u64t r; asm("mov.b64 %0, {%1, %2};" : "=l"(r) : "f"(lo), "f"(hi)); return r;
}
__device__ __forceinline__ float2 upk2(u64t v) {
    float2 r; asm("mov.b64 {%0, %1}, %2;" : "=f"(r.x), "=f"(r.y) : "l"(v)); return r;
}
#define FMA2(d, a, b) asm("fma.rn.f32x2 %0, %1, %2, %0;" : "+l"(d) : "l"(a), "l"(b))

__global__ __launch_bounds__(256, 1) void k_x0(const float* __restrict__ x,
                                               const float* __restrict__ b_in) {
    __shared__ float A_s[32][129];
    __shared__ float B_s[32][128];
    int tid = threadIdx.x;
    int r0 = blockIdx.x * 128;
    int c0 = blockIdx.y * 128;

    const float* Ag = x + (size_t)r0 * NX;
#pragma unroll
    for (int j = 0; j < 16; j++) {
        int idx = tid + j * 256;
        A_s[idx & 31][idx >> 5] = Ag[idx];
    }
#pragma unroll
    for (int j = 0; j < 16; j++) {
        int idx = tid + j * 256;
        int k = idx >> 7, col = idx & 127;
        B_s[k][col] = g_WinT[k * NH + c0 + col];
    }
    __syncthreads();

    int tx = tid & 7, ty = tid >> 3;
    int cb = tx * 16, rb = ty * 4;

    u64t acc[4][8];
#pragma unroll
    for (int p = 0; p < 8; p++) {
        u64t bp = pk2(b_in[c0 + cb + 2 * p], b_in[c0 + cb + 2 * p + 1]);
        acc[0][p] = bp; acc[1][p] = bp; acc[2][p] = bp; acc[3][p] = bp;
    }
#pragma unroll
    for (int kk = 0; kk < 32; kk++) {
        u64t a2[4];
#pragma unroll
        for (int i = 0; i < 4; i++) { float a = A_s[kk][rb + i]; a2[i] = pk2(a, a); }
        const u64t* bs = reinterpret_cast<const u64t*>(&B_s[kk][cb]);
        u64t b2[8];
#pragma unroll
        for (int p = 0; p < 8; p++) b2[p] = bs[p];
#pragma unroll
        for (int i = 0; i < 4; i++)
#pragma unroll
            for (int p = 0; p < 8; p++) FMA2(acc[i][p], a2[i], b2[p]);
    }
#pragma unroll
    for (int i = 0; i < 4; i++) {
        size_t r = (size_t)(r0 + rb + i);
        union { unsigned short s[16]; uint4 v[2]; } uh, ul;
#pragma unroll
        for (int p = 0; p < 8; p++) {
            float2 u = upk2(acc[i][p]);
            float f0 = fmaxf(u.x, 0.f), f1 = fmaxf(u.y, 0.f);
            __nv_bfloat16 h0 = __float2bfloat16(f0);
            __nv_bfloat16 h1 = __float2bfloat16(f1);
            __nv_bfloat16 l0 = __float2bfloat16(f0 - __bfloat162float(h0));
            __nv_bfloat16 l1 = __float2bfloat16(f1 - __bfloat162float(h1));
            uh.s[2 * p] = *(unsigned short*)&h0; uh.s[2 * p + 1] = *(unsigned short*)&h1;
            ul.s[2 * p] = *(unsigned short*)&l0; ul.s[2 * p + 1] = *(unsigned short*)&l1;
        }
        uint4* dh = (uint4*)(g_x0h + r * NH + c0 + cb);
        uint4* dl = (uint4*)(g_x0l + r * NH + c0 + cb);
        dh[0] = uh.v[0]; dh[1] = uh.v[1];
        dl[0] = ul.v[0]; dl[1] = ul.v[1];
    }
}

// ---------------- xg = x0 @ Wih^T + bias (HMMA, one chunk) ----------------
// grid (8 n-tiles, 146): each CTA does 8 M-tiles; Wih hi/lo resident in smem
__global__ __launch_bounds__(256, 1) void k_xgt(int chunk) {
    extern __shared__ char sm[];
    __shared__ float bias_s[128];
    uint32_t sb = smem_u32(sm);
    int tid = threadIdx.x, lane = tid & 31, w = tid >> 5;
    int wm = w >> 2, wn = w & 3;
    int g8 = lane >> 3, r8 = lane & 7;
    int rowAl = (g8 & 1) * 8 + r8, kselA = (g8 >> 1) * 8;
    int rowBl = (g8 >> 1) * 8 + r8, kselB = (g8 & 1) * 8;
    int gid = lane >> 2, tig = lane & 3;
    int n0 = blockIdx.x * 128;

    if (tid < 128) bias_s[tid] = g_biasr[n0 + tid];
#pragma unroll
    for (int kt = 0; kt < 4; kt++) {
        ld_tile(sb + kt * 16384,         g_Wih_h + (size_t)n0 * NH + kt * 64, tid);
        ld_tile(sb + 65536 + kt * 16384, g_Wih_l + (size_t)n0 * NH + kt * 64, tid);
    }

    for (int it = 0; it < 8; it++) {
        size_t mtile = (size_t)blockIdx.y * 8 + it;
        const __nv_bfloat16* ah = g_x0h + ((size_t)chunk * MCH + mtile * 128) * NH;
        const __nv_bfloat16* al = g_x0l + ((size_t)chunk * MCH + mtile * 128) * NH;

        float acc[4][4][4];
#pragma unroll
        for (int a = 0; a < 4; a++)
#pragma unroll
            for (int b = 0; b < 4; b++)
#pragma unroll
                for (int c = 0; c < 4; c++) acc[a][b][c] = 0.f;

        uint4 R[8];
        ldg_tile(R,     ah, tid);
        ldg_tile(R + 4, al, tid);
#pragma unroll 1
        for (int kt = 0; kt < 4; kt++) {
            uint32_t ab = sb + AOFF + (kt & 1) * 32768;
            sts_tile(ab, R, tid);
            sts_tile(ab + 16384, R + 4, tid);
            if (kt < 3) {
                ldg_tile(R,     ah + (kt + 1) * 64, tid);
                ldg_tile(R + 4, al + (kt + 1) * 64, tid);
            }
            __syncthreads();
            mma_chunk(ab, sb + kt * 16384, sb + 65536 + kt * 16384, acc,
                      wm * 64, wn * 32, rowAl, kselA, rowBl, kselB);
        }

        // epilogue: bias + store fp32
#pragma unroll
        for (int mf = 0; mf < 4; mf++)
#pragma unroll
            for (int nf = 0; nf < 4; nf++) {
                size_t row = mtile * 128 + wm * 64 + mf * 16 + gid;
                int coll = wn * 32 + nf * 8 + tig * 2;
                float b0 = bias_s[coll], b1 = bias_s[coll + 1];
                *(float2*)&g_xg[row * NG4 + n0 + coll] =
                    make_float2(acc[mf][nf][0] + b0, acc[mf][nf][1] + b1);
                *(float2*)&g_xg[(row + 8) * NG4 + n0 + coll] =
                    make_float2(acc[mf][nf][2] + b0, acc[mf][nf][3] + b1);
            }
        __syncthreads();
    }
}

// ---------------- persistent HMMA scan: 73 LSTM steps ----------------
__global__ __launch_bounds__(256, 1) void k_scan(int chunk, const float* __restrict__ W_out) {
    extern __shared__ char sm[];
    __shared__ float Wout_s[NH];
    uint32_t sb = smem_u32(sm);
    int tid = threadIdx.x, lane = tid & 31, w = tid >> 5;
    int wm = w >> 2, wn = w & 3;
    int g8 = lane >> 3, r8 = lane & 7;
    int rowAl = (g8 & 1) * 8 + r8, kselA = (g8 >> 1) * 8;
    int rowBl = (g8 >> 1) * 8 + r8, kselB = (g8 & 1) * 8;
    int gid = lane >> 2, tig = lane & 3;
    int nhat = blockIdx.x & 7, rbk = blockIdx.x >> 3;
    int n0 = nhat * 128, rbase = rbk * 128;

    Wout_s[tid] = W_out[tid];
#pragma unroll
    for (int kt = 0; kt < 4; kt++) {
        ld_tile(sb + kt * 16384,         g_Whh_h + (size_t)n0 * NH + kt * 64, tid);
        ld_tile(sb + 65536 + kt * 16384, g_Whh_l + (size_t)n0 * NH + kt * 64, tid);
    }

    // c state: creg[mf*4+nf] at (row = rbase+wm*64+mf*16+gid+(tig&1)*8,
    //                            h   = nhat*32+wn*8+nf*2+(tig>>1))
    float creg[16];
#pragma unroll
    for (int mf = 0; mf < 4; mf++)
#pragma unroll
        for (int nf = 0; nf < 4; nf++) {
            int row = rbase + wm * 64 + mf * 16 + gid + (tig & 1) * 8;
            int h = nhat * 32 + wn * 8 + nf * 2 + (tig >> 1);
            creg[mf * 4 + nf] = (chunk == 0) ? 0.f : g_c[row * NH + h];
        }
    __syncthreads();

    for (int tl = 0; tl < CHUNK; tl++) {
        int tg = chunk * CHUNK + tl;
        float acc[4][4][4];
#pragma unroll
        for (int a = 0; a < 4; a++)
#pragma unroll
            for (int b = 0; b < 4; b++)
#pragma unroll
                for (int c = 0; c < 4; c++) acc[a][b][c] = 0.f;

        if (tg > 0) {
            const __nv_bfloat16* hh = g_hh + (size_t)((tg - 1) & 1) * NGRID * NH + (size_t)rbase * NH;
            const __nv_bfloat16* hl = g_hl + (size_t)((tg - 1) & 1) * NGRID * NH + (size_t)rbase * NH;
            uint4 R[8];
            ldg_tile(R,     hh, tid);
            ldg_tile(R + 4, hl, tid);
#pragma unroll 1
            for (int kt = 0; kt < 4; kt++) {
                uint32_t ab = sb + AOFF + (kt & 1) * 32768;
                sts_tile(ab, R, tid);
                sts_tile(ab + 16384, R + 4, tid);
                if (kt < 3) {
                    ldg_tile(R,     hh + (kt + 1) * 64, tid);
                    ldg_tile(R + 4, hl + (kt + 1) * 64, tid);
                }
                __syncthreads();
                mma_chunk(ab, sb + kt * 16384, sb + 65536 + kt * 16384, acc,
                          wm * 64, wn * 32, rowAl, kselA, rowBl, kselB);
            }
        }

        // epilogue: reassemble gate quads, cell update, emit h hi/lo + out partials
        __nv_bfloat16* hhd = g_hh + (size_t)(tg & 1) * NGRID * NH;
        __nv_bfloat16* hld = g_hl + (size_t)(tg & 1) * NGRID * NH;
#pragma unroll
        for (int mf = 0; mf < 4; mf++) {
            int row = rbase + wm * 64 + mf * 16 + gid + (tig & 1) * 8;
            float pout = 0.f;
#pragma unroll
            for (int nf = 0; nf < 4; nf++) {
                float c0 = acc[mf][nf][0], c1 = acc[mf][nf][1];
                float c2 = acc[mf][nf][2], c3 = acc[mf][nf][3];
                float s0 = (lane & 1) ? c0 : c2;
                float s1 = (lane & 1) ? c1 : c3;
                float r0 = __shfl_xor_sync(0xffffffffu, s0, 1);
                float r1 = __shfl_xor_sync(0xffffffffu, s1, 1);
                float gi, gf, gg, go;
                if (!(lane & 1)) { gi = c0; gf = c1; gg = r0; go = r1; }
                else             { gi = r0; gf = r1; gg = c2; go = c3; }
                int hl_i = wn * 8 + nf * 2 + (tig >> 1);
                int h = nhat * 32 + hl_i;
                float4 xv = __ldcg((const float4*)&g_xg[((size_t)tl * NGRID + row) * NG4 + n0 + hl_i * 4]);
                float iv = gi + xv.x, fv = gf + xv.y, gv = gg + xv.z, ov = go + xv.w;
                float cn = sigf(fv) * creg[mf * 4 + nf] + sigf(iv) * tanhf(gv);
                creg[mf * 4 + nf] = cn;
                float hv = sigf(ov) * tanhf(cn);
                pout += hv * Wout_s[h];
                __nv_bfloat16 bh = __float2bfloat16(hv);
                __nv_bfloat16 bl = __float2bfloat16(hv - __bfloat162float(bh));
                hhd[(size_t)row * NH + h] = bh;
                hld[(size_t)row * NH + h] = bl;
            }
            float pr = pout + __shfl_xor_sync(0xffffffffu, pout, 2);
            if (tig < 2)
                g_part[((size_t)tg * NGRID + row) * 32 + nhat * 4 + wn] = pr;
        }

        grid_sync();
    }

    // spill c
#pragma unroll
    for (int mf = 0; mf < 4; mf++)
#pragma unroll
        for (int nf = 0; nf < 4; nf++) {
            int row = rbase + wm * 64 + mf * 16 + gid + (tig & 1) * 8;
            int h = nhat * 32 + wn * 8 + nf * 2 + (tig >> 1);
            g_c[row * NH + h] = creg[mf * 4 + nf];
        }
}

// ---------------- out = sum(32 partials) + b_out ----------------
__global__ __launch_bounds__(256) void k_out(const float* __restrict__ b_out,
                                             float* __restrict__ out) {
    size_t r = (size_t)blockIdx.x * 256 + threadIdx.x;
    const float4* p = (const float4*)(g_part + r * 32);
    float s = 0.f;
#pragma unroll
    for (int j = 0; j < 8; j++) {
        float4 v = p[j];
        s += v.x + v.y + v.z + v.w;
    }
    out[r] = s + b_out[0];
}

// ---------------- launch ----------------
extern "C" void kernel_launch(void* const* d_in, const int* in_sizes, int n_in,
                              void* d_out, int out_size) {
    const float* x     = (const float*)d_in[0];
    const float* W_in  = (const float*)d_in[1];
    const float* b_in  = (const float*)d_in[2];
    const float* W_ih  = (const float*)d_in[3];
    const float* b_ih  = (const float*)d_in[4];
    const float* W_hh  = (const float*)d_in[5];
    const float* b_hh  = (const float*)d_in[6];
    const float* W_out = (const float*)d_in[7];
    const float* b_out = (const float*)d_in[8];
    float* out = (float*)d_out;

    static int attr_done = 0;
    if (!attr_done) {
        cudaFuncSetAttribute(k_xgt,  cudaFuncAttributeMaxDynamicSharedMemorySize, DSMEM);
        cudaFuncSetAttribute(k_scan, cudaFuncAttributeMaxDynamicSharedMemorySize, DSMEM);
        attr_done = 1;
    }

    k_prep<<<(NG4 * NH + 255) / 256, 256>>>(W_in, W_ih, b_ih, b_hh, W_hh);
    k_x0<<<dim3(M_TOT / 128, NH / 128), 256>>>(x, b_in);
    for (int chunk = 0; chunk < NCHUNK; chunk++) {
        k_xgt<<<dim3(8, 146), 256, DSMEM>>>(chunk);
        k_scan<<<NBLK, 256, DSMEM>>>(chunk, W_out);
    }
    k_out<<<M_TOT / 256, 256>>>(b_out, out);
}

// round 6
// speedup vs baseline: 5.8295x; 1.1917x over previous
#include <cuda_runtime.h>
#include <cuda_bf16.h>
#include <math.h>
#include <stdint.h>

// ---------------- problem constants ----------------
#define NT    365
#define NGRID 2048
#define NX    32
#define NH    256
#define NG4   1024
#define M_TOT (NT * NGRID)        // 747520
#define CHUNK 73                  // 365 = 5*73
#define NCHUNK 5
#define MCH   (CHUNK * NGRID)     // 149504

// dynamic SMEM: W hi [0,64K), W lo [64K,128K), A bufs [128K,192K)
#define AOFF  131072
#define DSMEM 196608

// ---------------- device globals (~1.5 GB) ----------------
__device__ __nv_bfloat16 g_x0h[(size_t)M_TOT * NH];
__device__ __nv_bfloat16 g_x0l[(size_t)M_TOT * NH];
__device__ float g_xg[(size_t)MCH * NG4];             // per-chunk ring
__device__ __nv_bfloat16 g_hh[2 * NGRID * NH];        // h ring hi
__device__ __nv_bfloat16 g_hl[2 * NGRID * NH];        // h ring lo
__device__ float g_part[(size_t)M_TOT * 32];
__device__ float g_c[NGRID * NH];
__device__ float g_WinT[NX * NH];
__device__ __nv_bfloat16 g_Wih_h[NG4 * NH], g_Wih_l[NG4 * NH];  // [c][k], c=h*4+g
__device__ __nv_bfloat16 g_Whh_h[NG4 * NH], g_Whh_l[NG4 * NH];
__device__ float g_biasr[NG4];
__device__ unsigned g_gcnt[16 * 32];   // per-rbk-group barrier (padded)
__device__ unsigned g_ggen[16 * 32];

// ---------------- helpers ----------------
__device__ __forceinline__ float sigf(float x) { return 1.0f / (1.0f + expf(-x)); }

__device__ __forceinline__ uint32_t smem_u32(const void* p) {
    uint32_t a;
    asm("{ .reg .u64 t; cvta.to.shared.u64 t, %1; cvt.u32.u64 %0, t; }" : "=r"(a) : "l"(p));
    return a;
}
__device__ __forceinline__ uint32_t tadr(uint32_t tb, int row, int kcol) {
    uint32_t bo = (uint32_t)(row * 128 + kcol * 2);
    return tb + (bo ^ ((bo >> 3) & 0x70));
}
__device__ __forceinline__ void ldsm4(uint32_t* r, uint32_t addr) {
    asm volatile("ldmatrix.sync.aligned.m8n8.x4.shared.b16 {%0,%1,%2,%3}, [%4];"
                 : "=r"(r[0]), "=r"(r[1]), "=r"(r[2]), "=r"(r[3]) : "r"(addr));
}
__device__ __forceinline__ void mma16816(float* d, const uint32_t* a, const uint32_t* b) {
    asm volatile("mma.sync.aligned.m16n8k16.row.col.f32.bf16.bf16.f32 "
                 "{%0,%1,%2,%3}, {%4,%5,%6,%7}, {%8,%9}, {%0,%1,%2,%3};"
                 : "+f"(d[0]), "+f"(d[1]), "+f"(d[2]), "+f"(d[3])
                 : "r"(a[0]), "r"(a[1]), "r"(a[2]), "r"(a[3]), "r"(b[0]), "r"(b[1]));
}
__device__ __forceinline__ void pref_l2(const void* p) {
    asm volatile("prefetch.global.L2 [%0];" :: "l"(p));
}

// 512-thread tile movers: one 128x64 bf16 tile (row pitch 256 elems = 512B)
__device__ __forceinline__ void ldg_tile(uint4* R, const __nv_bfloat16* __restrict__ g, int tid) {
    const char* gp = (const char*)g;
#pragma unroll
    for (int j = 0; j < 2; j++) {
        int q = tid + j * 512;
        int row = q >> 3, ch = q & 7;
        R[j] = __ldcg((const uint4*)(gp + (size_t)row * 512 + ch * 16));
    }
}
__device__ __forceinline__ void sts_tile(uint32_t dst, const uint4* R, int tid) {
#pragma unroll
    for (int j = 0; j < 2; j++) {
        int q = tid + j * 512;
        int row = q >> 3, ch = q & 7;
        uint32_t bo = (uint32_t)(row * 128 + ch * 16);
        uint32_t off = dst + (bo ^ ((bo >> 3) & 0x70));
        asm volatile("st.shared.v4.b32 [%0], {%1,%2,%3,%4};"
                     :: "r"(off), "r"(R[j].x), "r"(R[j].y), "r"(R[j].z), "r"(R[j].w));
    }
}
__device__ __forceinline__ void ld_tile(uint32_t dst, const __nv_bfloat16* __restrict__ g, int tid) {
    uint4 R[2];
    ldg_tile(R, g, tid);
    sts_tile(dst, R, tid);
}

// one 64-wide K chunk, warp tile 32x32: 3-term split, 4 k16 steps
__device__ __forceinline__ void mma_chunk(uint32_t abuf, uint32_t whi, uint32_t wlo,
                                          float acc[2][4][4], int mrow, int nbase,
                                          int rowAl, int kselA, int rowBl, int kselB) {
    uint32_t ahi = abuf, alo = abuf + 16384;
#pragma unroll
    for (int ks = 0; ks < 4; ks++) {
        int kA = ks * 16 + kselA, kB = ks * 16 + kselB;
        uint32_t Ah[2][4], Al[2][4], Wh[2][4], Wl[2][4];
#pragma unroll
        for (int mf = 0; mf < 2; mf++) {
            int row = mrow + mf * 16 + rowAl;
            ldsm4(Ah[mf], tadr(ahi, row, kA));
            ldsm4(Al[mf], tadr(alo, row, kA));
        }
#pragma unroll
        for (int np = 0; np < 2; np++) {
            int n = nbase + np * 16 + rowBl;
            ldsm4(Wh[np], tadr(whi, n, kB));
            ldsm4(Wl[np], tadr(wlo, n, kB));
        }
#pragma unroll
        for (int mf = 0; mf < 2; mf++)
#pragma unroll
            for (int nf = 0; nf < 4; nf++) {
                const uint32_t* bh = &Wh[nf >> 1][(nf & 1) * 2];
                const uint32_t* bl = &Wl[nf >> 1][(nf & 1) * 2];
                mma16816(acc[mf][nf], Ah[mf], bh);
                mma16816(acc[mf][nf], Al[mf], bh);
                mma16816(acc[mf][nf], Ah[mf], bl);
            }
    }
}

// ---------------- per-rbk 8-CTA barrier ----------------
__device__ __forceinline__ void group_sync(int grp) {
    __syncthreads();
    if (threadIdx.x == 0) {
        __threadfence();
        volatile unsigned* genp = &g_ggen[grp * 32];
        unsigned gen = *genp;
        if (atomicAdd(&g_gcnt[grp * 32], 1u) == 7u) {
            g_gcnt[grp * 32] = 0;
            __threadfence();
            atomicExch((unsigned*)&g_ggen[grp * 32], gen + 1);
        } else {
            while (*genp == gen) __nanosleep(20);
        }
        __threadfence();
    }
    __syncthreads();
}

// ---------------- prep ----------------
__global__ void k_prep(const float* __restrict__ W_in,
                       const float* __restrict__ W_ih,
                       const float* __restrict__ b_ih,
                       const float* __restrict__ b_hh,
                       const float* __restrict__ W_hh) {
    int i = blockIdx.x * blockDim.x + threadIdx.x;
    if (i < NX * NH) {
        int k = i / NH, h = i % NH;
        g_WinT[k * NH + h] = W_in[h * NX + k];
    }
    if (i < NG4 * NH) {
        int c = i >> 8, k = i & 255;
        int h = c >> 2, g = c & 3;
        int n = g * NH + h;
        float wih = W_ih[n * NH + k];
        float whh = W_hh[n * NH + k];
        __nv_bfloat16 ih_h = __float2bfloat16(wih);
        __nv_bfloat16 hh_h = __float2bfloat16(whh);
        g_Wih_h[i] = ih_h;
        g_Wih_l[i] = __float2bfloat16(wih - __bfloat162float(ih_h));
        g_Whh_h[i] = hh_h;
        g_Whh_l[i] = __float2bfloat16(whh - __bfloat162float(hh_h));
    }
    if (i < NG4) {
        int h = i >> 2, g = i & 3;
        int n = g * NH + h;
        g_biasr[i] = b_ih[n] + b_hh[n];
    }
}

// ---------------- x0 = relu(x @ W_in^T + b_in) -> bf16 hi/lo ----------------
typedef unsigned long long u64t;
__device__ __forceinline__ u64t pk2(float lo, float hi) {
    u64t r; asm("mov.b64 %0, {%1, %2};" : "=l"(r) : "f"(lo), "f"(hi)); return r;
}
__device__ __forceinline__ float2 upk2(u64t v) {
    float2 r; asm("mov.b64 {%0, %1}, %2;" : "=f"(r.x), "=f"(r.y) : "l"(v)); return r;
}
#define FMA2(d, a, b) asm("fma.rn.f32x2 %0, %1, %2, %0;" : "+l"(d) : "l"(a), "l"(b))

__global__ __launch_bounds__(256, 1) void k_x0(const float* __restrict__ x,
                                               const float* __restrict__ b_in) {
    __shared__ float A_s[32][129];
    __shared__ float B_s[32][128];
    int tid = threadIdx.x;
    int r0 = blockIdx.x * 128;
    int c0 = blockIdx.y * 128;

    const float* Ag = x + (size_t)r0 * NX;
#pragma unroll
    for (int j = 0; j < 16; j++) {
        int idx = tid + j * 256;
        A_s[idx & 31][idx >> 5] = Ag[idx];
    }
#pragma unroll
    for (int j = 0; j < 16; j++) {
        int idx = tid + j * 256;
        int k = idx >> 7, col = idx & 127;
        B_s[k][col] = g_WinT[k * NH + c0 + col];
    }
    __syncthreads();

    int tx = tid & 7, ty = tid >> 3;
    int cb = tx * 16, rb = ty * 4;

    u64t acc[4][8];
#pragma unroll
    for (int p = 0; p < 8; p++) {
        u64t bp = pk2(b_in[c0 + cb + 2 * p], b_in[c0 + cb + 2 * p + 1]);
        acc[0][p] = bp; acc[1][p] = bp; acc[2][p] = bp; acc[3][p] = bp;
    }
#pragma unroll
    for (int kk = 0; kk < 32; kk++) {
        u64t a2[4];
#pragma unroll
        for (int i = 0; i < 4; i++) { float a = A_s[kk][rb + i]; a2[i] = pk2(a, a); }
        const u64t* bs = reinterpret_cast<const u64t*>(&B_s[kk][cb]);
        u64t b2[8];
#pragma unroll
        for (int p = 0; p < 8; p++) b2[p] = bs[p];
#pragma unroll
        for (int i = 0; i < 4; i++)
#pragma unroll
            for (int p = 0; p < 8; p++) FMA2(acc[i][p], a2[i], b2[p]);
    }
#pragma unroll
    for (int i = 0; i < 4; i++) {
        size_t r = (size_t)(r0 + rb + i);
        union { unsigned short s[16]; uint4 v[2]; } uh, ul;
#pragma unroll
        for (int p = 0; p < 8; p++) {
            float2 u = upk2(acc[i][p]);
            float f0 = fmaxf(u.x, 0.f), f1 = fmaxf(u.y, 0.f);
            __nv_bfloat16 h0 = __float2bfloat16(f0);
            __nv_bfloat16 h1 = __float2bfloat16(f1);
            __nv_bfloat16 l0 = __float2bfloat16(f0 - __bfloat162float(h0));
            __nv_bfloat16 l1 = __float2bfloat16(f1 - __bfloat162float(h1));
            uh.s[2 * p] = *(unsigned short*)&h0; uh.s[2 * p + 1] = *(unsigned short*)&h1;
            ul.s[2 * p] = *(unsigned short*)&l0; ul.s[2 * p + 1] = *(unsigned short*)&l1;
        }
        uint4* dh = (uint4*)(g_x0h + r * NH + c0 + cb);
        uint4* dl = (uint4*)(g_x0l + r * NH + c0 + cb);
        dh[0] = uh.v[0]; dh[1] = uh.v[1];
        dl[0] = ul.v[0]; dl[1] = ul.v[1];
    }
}

// ---------------- xg = x0 @ Wih^T + bias (HMMA, one chunk, 512 thr) ----------------
__global__ __launch_bounds__(512, 1) void k_xgt(int chunk) {
    extern __shared__ char sm[];
    __shared__ float bias_s[128];
    uint32_t sb = smem_u32(sm);
    int tid = threadIdx.x, lane = tid & 31, w = tid >> 5;
    int wm = w >> 2, wn = w & 3;
    int g8 = lane >> 3, r8 = lane & 7;
    int rowAl = (g8 & 1) * 8 + r8, kselA = (g8 >> 1) * 8;
    int rowBl = (g8 >> 1) * 8 + r8, kselB = (g8 & 1) * 8;
    int gid = lane >> 2, tig = lane & 3;
    int n0 = blockIdx.x * 128;

    if (tid < 128) bias_s[tid] = g_biasr[n0 + tid];
#pragma unroll
    for (int kt = 0; kt < 4; kt++) {
        ld_tile(sb + kt * 16384,         g_Wih_h + (size_t)n0 * NH + kt * 64, tid);
        ld_tile(sb + 65536 + kt * 16384, g_Wih_l + (size_t)n0 * NH + kt * 64, tid);
    }

    for (int it = 0; it < 8; it++) {
        size_t mtile = (size_t)blockIdx.y * 8 + it;
        const __nv_bfloat16* ah = g_x0h + ((size_t)chunk * MCH + mtile * 128) * NH;
        const __nv_bfloat16* al = g_x0l + ((size_t)chunk * MCH + mtile * 128) * NH;

        float acc[2][4][4];
#pragma unroll
        for (int a = 0; a < 2; a++)
#pragma unroll
            for (int b = 0; b < 4; b++)
#pragma unroll
                for (int c = 0; c < 4; c++) acc[a][b][c] = 0.f;

        uint4 R[4];
        ldg_tile(R,     ah, tid);
        ldg_tile(R + 2, al, tid);
#pragma unroll 1
        for (int kt = 0; kt < 4; kt++) {
            uint32_t ab = sb + AOFF + (kt & 1) * 32768;
            sts_tile(ab, R, tid);
            sts_tile(ab + 16384, R + 2, tid);
            if (kt < 3) {
                ldg_tile(R,     ah + (kt + 1) * 64, tid);
                ldg_tile(R + 2, al + (kt + 1) * 64, tid);
            }
            __syncthreads();
            mma_chunk(ab, sb + kt * 16384, sb + 65536 + kt * 16384, acc,
                      wm * 32, wn * 32, rowAl, kselA, rowBl, kselB);
        }

#pragma unroll
        for (int mf = 0; mf < 2; mf++)
#pragma unroll
            for (int nf = 0; nf < 4; nf++) {
                size_t row = mtile * 128 + wm * 32 + mf * 16 + gid;
                int coll = wn * 32 + nf * 8 + tig * 2;
                float b0 = bias_s[coll], b1 = bias_s[coll + 1];
                *(float2*)&g_xg[row * NG4 + n0 + coll] =
                    make_float2(acc[mf][nf][0] + b0, acc[mf][nf][1] + b1);
                *(float2*)&g_xg[(row + 8) * NG4 + n0 + coll] =
                    make_float2(acc[mf][nf][2] + b0, acc[mf][nf][3] + b1);
            }
        __syncthreads();
    }
}

// ---------------- persistent HMMA scan (512 thr, per-group barrier) ----------------
__global__ __launch_bounds__(512, 1) void k_scan(int chunk, const float* __restrict__ W_out) {
    extern __shared__ char sm[];
    __shared__ float Wout_s[NH];
    uint32_t sb = smem_u32(sm);
    int tid = threadIdx.x, lane = tid & 31, w = tid >> 5;
    int wm = w >> 2, wn = w & 3;
    int g8 = lane >> 3, r8 = lane & 7;
    int rowAl = (g8 & 1) * 8 + r8, kselA = (g8 >> 1) * 8;
    int rowBl = (g8 >> 1) * 8 + r8, kselB = (g8 & 1) * 8;
    int gid = lane >> 2, tig = lane & 3;
    int nhat = blockIdx.x & 7, rbk = blockIdx.x >> 3;
    int n0 = nhat * 128, rbase = rbk * 128;

    if (tid < NH) Wout_s[tid] = W_out[tid];
#pragma unroll
    for (int kt = 0; kt < 4; kt++) {
        ld_tile(sb + kt * 16384,         g_Whh_h + (size_t)n0 * NH + kt * 64, tid);
        ld_tile(sb + 65536 + kt * 16384, g_Whh_l + (size_t)n0 * NH + kt * 64, tid);
    }

    // c state: creg[mf][nf] at row = rbase+wm*32+mf*16+gid+(tig&1)*8,
    //                          h   = nhat*32+wn*8+nf*2+(tig>>1)
    float creg[2][4];
#pragma unroll
    for (int mf = 0; mf < 2; mf++)
#pragma unroll
        for (int nf = 0; nf < 4; nf++) {
            int row = rbase + wm * 32 + mf * 16 + gid + (tig & 1) * 8;
            int h = nhat * 32 + wn * 8 + nf * 2 + (tig >> 1);
            creg[mf][nf] = (chunk == 0) ? 0.f : g_c[row * NH + h];
        }
    __syncthreads();

    for (int tl = 0; tl < CHUNK; tl++) {
        int tg = chunk * CHUNK + tl;

        // prefetch this step's gate rows into L2
#pragma unroll
        for (int mf = 0; mf < 2; mf++) {
            int rloc = wm * 32 + mf * 16 + gid + (tig & 1) * 8;
            int row = rbase + rloc;
            pref_l2(&g_xg[((size_t)tl * NGRID + row) * NG4 + n0 + (wn * 8 + (tig >> 1)) * 4]);
        }

        float acc[2][4][4];
#pragma unroll
        for (int a = 0; a < 2; a++)
#pragma unroll
            for (int b = 0; b < 4; b++)
#pragma unroll
                for (int c = 0; c < 4; c++) acc[a][b][c] = 0.f;

        if (tg > 0) {
            const __nv_bfloat16* hh = g_hh + (size_t)((tg - 1) & 1) * NGRID * NH + (size_t)rbase * NH;
            const __nv_bfloat16* hl = g_hl + (size_t)((tg - 1) & 1) * NGRID * NH + (size_t)rbase * NH;
            uint4 R[4];
            ldg_tile(R,     hh, tid);
            ldg_tile(R + 2, hl, tid);
#pragma unroll 1
            for (int kt = 0; kt < 4; kt++) {
                uint32_t ab = sb + AOFF + (kt & 1) * 32768;
                sts_tile(ab, R, tid);
                sts_tile(ab + 16384, R + 2, tid);
                if (kt < 3) {
                    ldg_tile(R,     hh + (kt + 1) * 64, tid);
                    ldg_tile(R + 2, hl + (kt + 1) * 64, tid);
                }
                __syncthreads();
                mma_chunk(ab, sb + kt * 16384, sb + 65536 + kt * 16384, acc,
                          wm * 32, wn * 32, rowAl, kselA, rowBl, kselB);
            }
        }

        // epilogue: gate reassembly + cell update; stage h tile in smem
        uint32_t sh_hi = sb + AOFF;           // 128x32 bf16 = 8KB
        uint32_t sh_lo = sb + AOFF + 8192;
        __syncthreads();                       // all mma reads of A bufs done
#pragma unroll
        for (int mf = 0; mf < 2; mf++) {
            int rloc = wm * 32 + mf * 16 + gid + (tig & 1) * 8;
            int row = rbase + rloc;
            float pout = 0.f;
#pragma unroll
            for (int nf = 0; nf < 4; nf++) {
                float c0 = acc[mf][nf][0], c1 = acc[mf][nf][1];
                float c2 = acc[mf][nf][2], c3 = acc[mf][nf][3];
                float s0 = (lane & 1) ? c0 : c2;
                float s1 = (lane & 1) ? c1 : c3;
                float r0 = __shfl_xor_sync(0xffffffffu, s0, 1);
                float r1 = __shfl_xor_sync(0xffffffffu, s1, 1);
                float gi, gf, gg, go;
                if (!(lane & 1)) { gi = c0; gf = c1; gg = r0; go = r1; }
                else             { gi = r0; gf = r1; gg = c2; go = c3; }
                int hl_i = wn * 8 + nf * 2 + (tig >> 1);
                float4 xv = __ldcg((const float4*)&g_xg[((size_t)tl * NGRID + row) * NG4 + n0 + hl_i * 4]);
                float iv = gi + xv.x, fv = gf + xv.y, gv = gg + xv.z, ov = go + xv.w;
                float cn = sigf(fv) * creg[mf][nf] + sigf(iv) * tanhf(gv);
                creg[mf][nf] = cn;
                float hv = sigf(ov) * tanhf(cn);
                pout += hv * Wout_s[nhat * 32 + hl_i];
                __nv_bfloat16 bh = __float2bfloat16(hv);
                __nv_bfloat16 bl = __float2bfloat16(hv - __bfloat162float(bh));
                uint32_t so = (uint32_t)(rloc * 64 + hl_i * 2);
                asm volatile("st.shared.u16 [%0], %1;" :: "r"(sh_hi + so), "h"(*(unsigned short*)&bh));
                asm volatile("st.shared.u16 [%0], %1;" :: "r"(sh_lo + so), "h"(*(unsigned short*)&bl));
            }
            float pr = pout + __shfl_xor_sync(0xffffffffu, pout, 2);
            if ((tig >> 1) == 0)
                g_part[((size_t)tg * NGRID + row) * 32 + nhat * 4 + wn] = pr;
        }
        __syncthreads();

        // coalesced h writeout: 128 rows x 32 cols hi/lo
        {
            int row = tid >> 2, seg = tid & 3;
            uint4 vh, vl;
            asm volatile("ld.shared.v4.b32 {%0,%1,%2,%3}, [%4];"
                         : "=r"(vh.x), "=r"(vh.y), "=r"(vh.z), "=r"(vh.w)
                         : "r"(sh_hi + row * 64 + seg * 16));
            asm volatile("ld.shared.v4.b32 {%0,%1,%2,%3}, [%4];"
                         : "=r"(vl.x), "=r"(vl.y), "=r"(vl.z), "=r"(vl.w)
                         : "r"(sh_lo + row * 64 + seg * 16));
            size_t go = (size_t)(tg & 1) * NGRID * NH + (size_t)(rbase + row) * NH + nhat * 32 + seg * 8;
            *(uint4*)(g_hh + go) = vh;
            *(uint4*)(g_hl + go) = vl;
        }

        if (tl < CHUNK - 1) group_sync(rbk);
    }

    // spill c
#pragma unroll
    for (int mf = 0; mf < 2; mf++)
#pragma unroll
        for (int nf = 0; nf < 4; nf++) {
            int row = rbase + wm * 32 + mf * 16 + gid + (tig & 1) * 8;
            int h = nhat * 32 + wn * 8 + nf * 2 + (tig >> 1);
            g_c[row * NH + h] = creg[mf][nf];
        }
}

// ---------------- out = sum(32 partials) + b_out ----------------
__global__ __launch_bounds__(256) void k_out(const float* __restrict__ b_out,
                                             float* __restrict__ out) {
    size_t r = (size_t)blockIdx.x * 256 + threadIdx.x;
    const float4* p = (const float4*)(g_part + r * 32);
    float s = 0.f;
#pragma unroll
    for (int j = 0; j < 8; j++) {
        float4 v = p[j];
        s += v.x + v.y + v.z + v.w;
    }
    out[r] = s + b_out[0];
}

// ---------------- launch ----------------
extern "C" void kernel_launch(void* const* d_in, const int* in_sizes, int n_in,
                              void* d_out, int out_size) {
    const float* x     = (const float*)d_in[0];
    const float* W_in  = (const float*)d_in[1];
    const float* b_in  = (const float*)d_in[2];
    const float* W_ih  = (const float*)d_in[3];
    const float* b_ih  = (const float*)d_in[4];
    const float* W_hh  = (const float*)d_in[5];
    const float* b_hh  = (const float*)d_in[6];
    const float* W_out = (const float*)d_in[7];
    const float* b_out = (const float*)d_in[8];
    float* out = (float*)d_out;

    static int attr_done = 0;
    if (!attr_done) {
        cudaFuncSetAttribute(k_xgt,  cudaFuncAttributeMaxDynamicSharedMemorySize, DSMEM);
        cudaFuncSetAttribute(k_scan, cudaFuncAttributeMaxDynamicSharedMemorySize, DSMEM);
        attr_done = 1;
    }

    k_prep<<<(NG4 * NH + 255) / 256, 256>>>(W_in, W_ih, b_ih, b_hh, W_hh);
    k_x0<<<dim3(M_TOT / 128, NH / 128), 256>>>(x, b_in);
    for (int chunk = 0; chunk < NCHUNK; chunk++) {
        k_xgt<<<dim3(8, 146), 512, DSMEM>>>(chunk);
        k_scan<<<128, 512, DSMEM>>>(chunk, W_out);
    }
    k_out<<<M_TOT / 256, 256>>>(b_out, out);
}